// round 2
// baseline (speedup 1.0000x reference)
#include <cuda_runtime.h>
#include <math.h>
#include <stdint.h>

#define B_BATCH 2
#define NPTS    20480
#define MPTS    2048
#define CDIM    256
#define ND      16384
#define NS      512
#define NVIEW   800
#define GTH     0.001f

#define TFPS    512
#define PMAX    22                /* points per thread (fast path) */
#define NVMAX   (TFPS*PMAX)       /* 11264 compacted-point capacity */

/* output offsets (floats), concatenated in reference return order */
#define O_XYZ   0
#define O_FEAT  (B_BATCH*MPTS*3)                    /* 12288    */
#define O_AFF   (O_FEAT + B_BATCH*MPTS*CDIM)        /* 1060864  */
#define O_VIEW  (O_AFF + B_BATCH*ND)                /* 1093632  */
#define O_GRASP (O_VIEW + B_BATCH*NS*NVIEW)         /* 1912832  */

typedef unsigned long long ull;

__device__ float g_views[NVIEW*3];
__device__ int   g_oi[B_BATCH*NPTS];     /* compacted -> original index */
__device__ float g_cc[B_BATCH*NPTS*3];   /* fallback compacted coords   */
__device__ int   g_fps[B_BATCH*MPTS];    /* FPS-selected original idx   */
__device__ int   g_vind[B_BATCH*NS*3];   /* per-approach best view      */

/* ---------- packed f32x2 helpers (per-lane identical to scalar .rn) ---------- */
__device__ __forceinline__ ull pk2(float a, float b){
    ull r; asm("mov.b64 %0, {%1,%2};" : "=l"(r) : "f"(a), "f"(b)); return r;
}
__device__ __forceinline__ void upk2(ull v, float &a, float &b){
    asm("mov.b64 {%0,%1}, %2;" : "=f"(a), "=f"(b) : "l"(v));
}
__device__ __forceinline__ ull add2(ull a, ull b){
    ull r; asm("add.rn.f32x2 %0, %1, %2;" : "=l"(r) : "l"(a), "l"(b)); return r;
}
__device__ __forceinline__ ull mul2(ull a, ull b){
    ull r; asm("mul.rn.f32x2 %0, %1, %2;" : "=l"(r) : "l"(a), "l"(b)); return r;
}

/* ---------- view templates: fp64 Fibonacci sphere, matches numpy ---------- */
__global__ void views_kernel(){
    const double phi = (sqrt(5.0) - 1.0) * 0.5;
    for (int i = threadIdx.x; i < NVIEW; i += blockDim.x){
        double zi = (2.0 * (double)i + 1.0) / (double)NVIEW - 1.0;
        double r2 = 1.0 - zi * zi; if (r2 < 0.0) r2 = 0.0;
        double r  = sqrt(r2);
        double ang = 2.0 * 3.141592653589793 * (double)i * phi;
        g_views[i*3+0] = (float)(r * cos(ang));
        g_views[i*3+1] = (float)(r * sin(ang));
        g_views[i*3+2] = (float)zi;
    }
}

/* ---------- zero-fill the scatter outputs (128-bit stores) ---------- */
__global__ void zero_kernel(float4* __restrict__ p, size_t n4){
    size_t stride = (size_t)gridDim.x * blockDim.x;
    for (size_t i = (size_t)blockIdx.x * blockDim.x + threadIdx.x; i < n4; i += stride)
        p[i] = make_float4(0.f, 0.f, 0.f, 0.f);
}

/* ---------- block argmax: value desc, tie -> lower index ---------- */
__device__ __forceinline__ int block_argmax(float bestd, int bestc,
                                            float* redD, int* redC, int* bci, int t){
    #pragma unroll
    for (int off = 16; off > 0; off >>= 1){
        float od = __shfl_down_sync(0xffffffffu, bestd, off);
        int   oc = __shfl_down_sync(0xffffffffu, bestc, off);
        if (od > bestd || (od == bestd && oc < bestc)){ bestd = od; bestc = oc; }
    }
    if ((t & 31) == 0){ redD[t>>5] = bestd; redC[t>>5] = bestc; }
    __syncthreads();
    if (t < 32){
        float bd  = (t < 16) ? redD[t] : -3.3e38f;
        int   bcv = (t < 16) ? redC[t] : 0x7fffffff;
        #pragma unroll
        for (int off = 8; off > 0; off >>= 1){
            float od = __shfl_down_sync(0xffffffffu, bd, off);
            int   oc = __shfl_down_sync(0xffffffffu, bcv, off);
            if (od > bd || (od == bd && oc < bcv)){ bd = od; bcv = oc; }
        }
        if (t == 0) *bci = bcv;
    }
    __syncthreads();
    return *bci;
}

/* ---------- masked FPS, one block per batch ---------- */
__global__ void __launch_bounds__(TFPS, 1)
fps_kernel(const float* __restrict__ xyz, const float* __restrict__ gsc){
    extern __shared__ unsigned char fsm[];
    const int b = blockIdx.x;
    const int t = threadIdx.x;
    const float* X = xyz + (size_t)b * NPTS * 3;
    const float* G = gsc + (size_t)b * NPTS;

    float* xs   = (float*)fsm;                 /* [NVMAX] */
    float* ys   = xs + NVMAX;
    float* zs   = ys + NVMAX;
    int*   scan = (int*)(zs + NVMAX);          /* [TFPS]  */
    float* redD = (float*)(scan + TFPS);       /* [16]    */
    int*   redC = (int*)(redD + 16);           /* [16]    */
    int*   bci  = redC + 16;                   /* [1]     */

    /* ---- order-preserving compaction of graspable points ---- */
    const int CH = NPTS / TFPS;  /* 40 */
    int base = t * CH;
    int cnt = 0;
    for (int j = 0; j < CH; j++) cnt += (G[base + j] > GTH) ? 1 : 0;
    scan[t] = cnt;
    __syncthreads();
    for (int off = 1; off < TFPS; off <<= 1){
        int v = scan[t];
        int a = (t >= off) ? scan[t - off] : 0;
        __syncthreads();
        scan[t] = v + a;
        __syncthreads();
    }
    int Nv  = scan[TFPS - 1];
    int pos = scan[t] - cnt;
    bool fast = (Nv <= NVMAX);
    for (int j = 0; j < CH; j++){
        int idx = base + j;
        if (G[idx] > GTH){
            float x = X[idx*3+0], y = X[idx*3+1], z = X[idx*3+2];
            if (fast){
                xs[pos] = x; ys[pos] = y; zs[pos] = z;
            } else {
                size_t gp = ((size_t)b * NPTS + pos) * 3;
                g_cc[gp] = x; g_cc[gp+1] = y; g_cc[gp+2] = z;
            }
            g_oi[b*NPTS + pos] = idx;
            pos++;
        }
    }
    __syncthreads();
    if (Nv <= 0) return;

    if (fast){
        /* register-resident points; pads mirror point 0 (dist hits 0 after
           round 1, ties resolve to lower index, so pads can never win)  */
        ull Xp[PMAX/2], Yp[PMAX/2], Zp[PMAX/2];
        float D[PMAX];
        #pragma unroll
        for (int p = 0; p < PMAX/2; p++){
            int c0 = t + (2*p) * TFPS;
            int c1 = c0 + TFPS;
            int a0 = (c0 < Nv) ? c0 : 0;
            int a1 = (c1 < Nv) ? c1 : 0;
            Xp[p] = pk2(xs[a0], xs[a1]);
            Yp[p] = pk2(ys[a0], ys[a1]);
            Zp[p] = pk2(zs[a0], zs[a1]);
            D[2*p] = 1e10f; D[2*p+1] = 1e10f;
        }
        if (t == 0) g_fps[b*MPTS] = g_oi[b*NPTS];
        float px = xs[0], py = ys[0], pz = zs[0];

        for (int m = 1; m < MPTS; m++){
            ull nx = pk2(-px, -px), ny = pk2(-py, -py), nz = pk2(-pz, -pz);
            float bestd = -1.0f;
            #pragma unroll
            for (int p = 0; p < PMAX/2; p++){
                ull dx = add2(Xp[p], nx);               /* x - px        */
                ull dy = add2(Yp[p], ny);
                ull dz = add2(Zp[p], nz);
                ull s  = add2(add2(mul2(dx,dx), mul2(dy,dy)), mul2(dz,dz));
                float d0, d1; upk2(s, d0, d1);
                float n0 = fminf(D[2*p],   d0);
                float n1 = fminf(D[2*p+1], d1);
                D[2*p] = n0; D[2*p+1] = n1;
                bestd = fmaxf(bestd, n0);
                bestd = fmaxf(bestd, n1);
            }
            int bi = 0;
            #pragma unroll
            for (int i = PMAX-1; i >= 0; i--) if (D[i] == bestd) bi = i;
            int bestc = t + bi * TFPS;

            int wc = block_argmax(bestd, bestc, redD, redC, bci, t);
            if (t == 0) g_fps[b*MPTS + m] = g_oi[b*NPTS + wc];
            px = xs[wc]; py = ys[wc]; pz = zs[wc];
        }
    } else {
        /* fallback: dists in smem (reuse coord region), coords from global */
        float* dst = xs;
        for (int c = t; c < Nv; c += TFPS) dst[c] = 1e10f;
        if (t == 0) g_fps[b*MPTS] = g_oi[b*NPTS];
        __syncthreads();
        float px = g_cc[(size_t)b*NPTS*3+0];
        float py = g_cc[(size_t)b*NPTS*3+1];
        float pz = g_cc[(size_t)b*NPTS*3+2];
        for (int m = 1; m < MPTS; m++){
            float bestd = -1.0f; int bestc = 0x7fffffff;
            for (int c = t; c < Nv; c += TFPS){
                const float* P = &g_cc[((size_t)b*NPTS + c)*3];
                float dx = __fadd_rn(P[0], -px);
                float dy = __fadd_rn(P[1], -py);
                float dz = __fadd_rn(P[2], -pz);
                float d  = __fadd_rn(__fadd_rn(__fmul_rn(dx,dx), __fmul_rn(dy,dy)),
                                     __fmul_rn(dz,dz));
                float nd = fminf(dst[c], d);
                dst[c] = nd;
                if (nd > bestd){ bestd = nd; bestc = c; }
            }
            int wc = block_argmax(bestd, bestc, redD, redC, bci, t);
            if (t == 0) g_fps[b*MPTS + m] = g_oi[b*NPTS + wc];
            const float* P = &g_cc[((size_t)b*NPTS + wc)*3];
            px = P[0]; py = P[1]; pz = P[2];
            __syncthreads();
        }
    }
}

/* ---------- gather xyz + features by FPS indices ---------- */
__global__ void gather_kernel(const float* __restrict__ xyz, const float* __restrict__ feat,
                              float* __restrict__ oxyz, float* __restrict__ ofeat){
    int m = blockIdx.x, b = blockIdx.y;
    int j = g_fps[b*MPTS + m];
    int c = threadIdx.x;
    ofeat[((size_t)(b*MPTS + m))*CDIM + c] = feat[((size_t)b*NPTS + j)*CDIM + c];
    if (c < 3)
        oxyz[((size_t)(b*MPTS + m))*3 + c] = xyz[((size_t)b*NPTS + j)*3 + c];
}

/* ---------- stage 2: 2-NN affordance (d2 = sn + sq - 2*dot, as written) ---------- */
__global__ void nn_kernel(const float* __restrict__ dense, const float* __restrict__ sparse,
                          const float* __restrict__ scores, float* __restrict__ aff){
    __shared__ float sx[NS], sy[NS], sz[NS], sq[NS], sc[NS];
    __shared__ unsigned char sv[NS];
    int b = blockIdx.y;
    for (int i = threadIdx.x; i < NS; i += blockDim.x){
        float x = sparse[((size_t)b*NS + i)*3+0];
        float y = sparse[((size_t)b*NS + i)*3+1];
        float z = sparse[((size_t)b*NS + i)*3+2];
        sx[i]=x; sy[i]=y; sz[i]=z;
        sq[i] = __fadd_rn(__fadd_rn(__fmul_rn(x,x), __fmul_rn(y,y)), __fmul_rn(z,z));
        sv[i] = (x != 0.f || y != 0.f || z != 0.f) ? 1 : 0;
        sc[i] = scores[b*NS + i];
    }
    __syncthreads();
    int j = blockIdx.x * blockDim.x + threadIdx.x;
    float x = dense[((size_t)b*ND + j)*3+0];
    float y = dense[((size_t)b*ND + j)*3+1];
    float z = dense[((size_t)b*ND + j)*3+2];
    float sn = __fadd_rn(__fadd_rn(__fmul_rn(x,x), __fmul_rn(y,y)), __fmul_rn(z,z));
    float d1 = 3.3e38f, d2 = 3.3e38f; int i1 = 0, i2 = 0;
    for (int i = 0; i < NS; i++){
        float dot = __fadd_rn(__fadd_rn(__fmul_rn(x,sx[i]), __fmul_rn(y,sy[i])),
                              __fmul_rn(z,sz[i]));
        float dd  = sv[i] ? __fadd_rn(__fadd_rn(sn, sq[i]), __fmul_rn(-2.0f, dot)) : 1e10f;
        if (dd < d1){ d2 = d1; i2 = i1; d1 = dd; i1 = i; }
        else if (dd < d2){ d2 = dd; i2 = i; }
    }
    aff[b*ND + j] = __fmul_rn(__fadd_rn(sc[i1], sc[i2]), 0.5f);
}

/* ---------- stage 3a: best view per approach dir (argmax dot, tie->first) ---------- */
__global__ void vmax_kernel(const float* __restrict__ appr){
    int gtid = blockIdx.x * blockDim.x + threadIdx.x;
    int wid  = gtid >> 5;
    int lane = gtid & 31;
    if (wid >= B_BATCH*NS*3) return;
    const float* a = appr + (size_t)wid * 3;
    float ax = a[0], ay = a[1], az = a[2];
    float bm = -3.3e38f; int bv = 0x7fffffff;
    for (int v = lane; v < NVIEW; v += 32){
        float d = __fadd_rn(__fadd_rn(__fmul_rn(ax, g_views[v*3+0]),
                                      __fmul_rn(ay, g_views[v*3+1])),
                            __fmul_rn(az, g_views[v*3+2]));
        if (d > bm){ bm = d; bv = v; }
    }
    #pragma unroll
    for (int off = 16; off > 0; off >>= 1){
        float od = __shfl_down_sync(0xffffffffu, bm, off);
        int   ov = __shfl_down_sync(0xffffffffu, bv, off);
        if (od > bm || (od == bm && ov < bv)){ bm = od; bv = ov; }
    }
    if (lane == 0) g_vind[wid] = bv;
}

/* ---------- stage 3b: scatter (one thread per (b,n); k ascending -> last wins) ---------- */
__global__ void scatter_kernel(const float* __restrict__ sparse,
                               const float* __restrict__ nvs,
                               const float* __restrict__ ngs,
                               float* __restrict__ vs_out,
                               float* __restrict__ gs_out){
    int idx = blockIdx.x * blockDim.x + threadIdx.x;   /* b*NS + n */
    if (idx >= B_BATCH*NS) return;
    const float* sp = sparse + (size_t)idx * 3;
    float vm = (sp[0] != 0.f || sp[1] != 0.f || sp[2] != 0.f) ? 1.f : 0.f;
    for (int k = 0; k < 3; k++){
        int v = g_vind[idx*3 + k];
        vs_out[(size_t)idx*NVIEW + v] = __fmul_rn(nvs[idx*3 + k], vm);
        const float* src = ngs + ((size_t)(idx*3 + k)) * 84;
        float* dst = gs_out + ((size_t)idx*NVIEW + v) * 84;
        for (int j = 0; j < 84; j++) dst[j] = __fmul_rn(src[j], vm);
    }
}

extern "C" void kernel_launch(void* const* d_in, const int* in_sizes, int n_in,
                              void* d_out, int out_size){
    const float* seed_xyz   = (const float*)d_in[0];
    const float* seed_feat  = (const float*)d_in[1];
    const float* graspness  = (const float*)d_in[2];
    const float* dense      = (const float*)d_in[3];
    const float* sparse     = (const float*)d_in[4];
    const float* nscores    = (const float*)d_in[5];
    const float* appr       = (const float*)d_in[6];
    const float* nviewsc    = (const float*)d_in[7];
    const float* ngraspsc   = (const float*)d_in[8];
    float* out = (float*)d_out;

    /* zero-fill scatter targets: (O_TOTAL - O_VIEW) floats, 16B-aligned */
    {
        size_t n4 = (size_t)(B_BATCH*NS*NVIEW + B_BATCH*NS*NVIEW*84) / 4;
        zero_kernel<<<2048, 256>>>((float4*)(out + O_VIEW), n4);
    }
    views_kernel<<<1, 256>>>();

    static int smem_set = 0;
    size_t fps_smem = 3*(size_t)NVMAX*4 + TFPS*4 + 16*4 + 16*4 + 64;
    if (!smem_set){
        cudaFuncSetAttribute(fps_kernel, cudaFuncAttributeMaxDynamicSharedMemorySize,
                             (int)fps_smem);
        smem_set = 1;
    }
    fps_kernel<<<B_BATCH, TFPS, fps_smem>>>(seed_xyz, graspness);
    gather_kernel<<<dim3(MPTS, B_BATCH), CDIM>>>(seed_xyz, seed_feat,
                                                 out + O_XYZ, out + O_FEAT);
    nn_kernel<<<dim3(ND/256, B_BATCH), 256>>>(dense, sparse, nscores, out + O_AFF);
    vmax_kernel<<<(B_BATCH*NS*3*32 + 255)/256, 256>>>(appr);
    scatter_kernel<<<(B_BATCH*NS + 255)/256, 256>>>(sparse, nviewsc, ngraspsc,
                                                    out + O_VIEW, out + O_GRASP);
    (void)in_sizes; (void)n_in; (void)out_size;
}

// round 3
// speedup vs baseline: 1.6475x; 1.6475x over previous
#include <cuda_runtime.h>
#include <math.h>
#include <stdint.h>

#define B_BATCH 2
#define NPTS    20480
#define MPTS    2048
#define CDIM    256
#define ND      16384
#define NS      512
#define NVIEW   800
#define GTH     0.001f

#define TFPS    512
#define PMAX    22                /* points per thread (fast path) */
#define NVMAX   (TFPS*PMAX)       /* 11264 compacted-point capacity */

/* output offsets (floats), concatenated in reference return order */
#define O_XYZ   0
#define O_FEAT  (B_BATCH*MPTS*3)                    /* 12288    */
#define O_AFF   (O_FEAT + B_BATCH*MPTS*CDIM)        /* 1060864  */
#define O_VIEW  (O_AFF + B_BATCH*ND)                /* 1093632  */
#define O_GRASP (O_VIEW + B_BATCH*NS*NVIEW)         /* 1912832  */

typedef unsigned long long ull;

__device__ float g_views[NVIEW*3];
__device__ int   g_oi[B_BATCH*NPTS];     /* compacted -> original index */
__device__ float g_cc[B_BATCH*NPTS*3];   /* fallback compacted coords   */
__device__ int   g_fps[B_BATCH*MPTS];    /* FPS-selected original idx   */
__device__ int   g_vind[B_BATCH*NS*3];   /* per-approach best view      */

/* ---------- packed f32x2 helpers (per-lane identical to scalar .rn) ---------- */
__device__ __forceinline__ ull pk2(float a, float b){
    ull r; asm("mov.b64 %0, {%1,%2};" : "=l"(r) : "f"(a), "f"(b)); return r;
}
__device__ __forceinline__ void upk2(ull v, float &a, float &b){
    asm("mov.b64 {%0,%1}, %2;" : "=f"(a), "=f"(b) : "l"(v));
}
__device__ __forceinline__ ull add2(ull a, ull b){
    ull r; asm("add.rn.f32x2 %0, %1, %2;" : "=l"(r) : "l"(a), "l"(b)); return r;
}
__device__ __forceinline__ ull mul2(ull a, ull b){
    ull r; asm("mul.rn.f32x2 %0, %1, %2;" : "=l"(r) : "l"(a), "l"(b)); return r;
}

/* ---------- view templates: fp64 Fibonacci sphere, matches numpy ---------- */
__global__ void views_kernel(){
    const double phi = (sqrt(5.0) - 1.0) * 0.5;
    for (int i = threadIdx.x; i < NVIEW; i += blockDim.x){
        double zi = (2.0 * (double)i + 1.0) / (double)NVIEW - 1.0;
        double r2 = 1.0 - zi * zi; if (r2 < 0.0) r2 = 0.0;
        double r  = sqrt(r2);
        double ang = 2.0 * 3.141592653589793 * (double)i * phi;
        g_views[i*3+0] = (float)(r * cos(ang));
        g_views[i*3+1] = (float)(r * sin(ang));
        g_views[i*3+2] = (float)zi;
    }
}

/* ---------- zero-fill the scatter outputs (128-bit stores) ---------- */
__global__ void zero_kernel(float4* __restrict__ p, size_t n4){
    size_t stride = (size_t)gridDim.x * blockDim.x;
    for (size_t i = (size_t)blockIdx.x * blockDim.x + threadIdx.x; i < n4; i += stride)
        p[i] = make_float4(0.f, 0.f, 0.f, 0.f);
}

/* ---------- generic block argmax (fallback path only) ---------- */
__device__ __forceinline__ int block_argmax(float bestd, int bestc,
                                            float* redD, int* redC, int* bci, int t){
    #pragma unroll
    for (int off = 16; off > 0; off >>= 1){
        float od = __shfl_down_sync(0xffffffffu, bestd, off);
        int   oc = __shfl_down_sync(0xffffffffu, bestc, off);
        if (od > bestd || (od == bestd && oc < bestc)){ bestd = od; bestc = oc; }
    }
    if ((t & 31) == 0){ redD[t>>5] = bestd; redC[t>>5] = bestc; }
    __syncthreads();
    if (t < 32){
        float bd  = (t < 16) ? redD[t] : -3.3e38f;
        int   bcv = (t < 16) ? redC[t] : 0x7fffffff;
        #pragma unroll
        for (int off = 8; off > 0; off >>= 1){
            float od = __shfl_down_sync(0xffffffffu, bd, off);
            int   oc = __shfl_down_sync(0xffffffffu, bcv, off);
            if (od > bd || (od == bd && oc < bcv)){ bd = od; bcv = oc; }
        }
        if (t == 0) *bci = bcv;
    }
    __syncthreads();
    return *bci;
}

/* ---------- masked FPS, one block per batch ---------- */
__global__ void __launch_bounds__(TFPS, 1)
fps_kernel(const float* __restrict__ xyz, const float* __restrict__ gsc){
    extern __shared__ unsigned char fsm[];
    const int b = blockIdx.x;
    const int t = threadIdx.x;
    const int lane = t & 31;
    const int w = t >> 5;
    const float* X = xyz + (size_t)b * NPTS * 3;
    const float* G = gsc + (size_t)b * NPTS;

    float*    xs   = (float*)fsm;               /* [NVMAX] */
    float*    ys   = xs + NVMAX;
    float*    zs   = ys + NVMAX;
    int*      scan = (int*)(zs + NVMAX);        /* [TFPS]  */
    unsigned* redW = (unsigned*)(scan + TFPS);  /* [16]    */
    int*      bciA = (int*)(redW + 16);         /* [2]     */

    /* ---- order-preserving compaction of graspable points ---- */
    const int CH = NPTS / TFPS;  /* 40 */
    int base = t * CH;
    int cnt = 0;
    for (int j = 0; j < CH; j++) cnt += (G[base + j] > GTH) ? 1 : 0;
    scan[t] = cnt;
    __syncthreads();
    for (int off = 1; off < TFPS; off <<= 1){
        int v = scan[t];
        int a = (t >= off) ? scan[t - off] : 0;
        __syncthreads();
        scan[t] = v + a;
        __syncthreads();
    }
    int Nv  = scan[TFPS - 1];
    int pos = scan[t] - cnt;
    bool fast = (Nv <= NVMAX);
    for (int j = 0; j < CH; j++){
        int idx = base + j;
        if (G[idx] > GTH){
            float x = X[idx*3+0], y = X[idx*3+1], z = X[idx*3+2];
            if (fast){
                xs[pos] = x; ys[pos] = y; zs[pos] = z;
            } else {
                size_t gp = ((size_t)b * NPTS + pos) * 3;
                g_cc[gp] = x; g_cc[gp+1] = y; g_cc[gp+2] = z;
            }
            g_oi[b*NPTS + pos] = idx;
            pos++;
        }
    }
    if (t == 0){ bciA[0] = 0x7fffffff; bciA[1] = 0x7fffffff; }
    __syncthreads();
    if (Nv <= 0) return;

    if (fast){
        /* register-resident points; pads mirror point 0 (their distance mirrors
           point 0's, and any index tie resolves to the true index 0)        */
        ull Xp[PMAX/2], Yp[PMAX/2], Zp[PMAX/2];
        unsigned Du[PMAX];
        #pragma unroll
        for (int p = 0; p < PMAX/2; p++){
            int c0 = t + (2*p) * TFPS;
            int c1 = c0 + TFPS;
            int a0 = (c0 < Nv) ? c0 : 0;
            int a1 = (c1 < Nv) ? c1 : 0;
            Xp[p] = pk2(xs[a0], xs[a1]);
            Yp[p] = pk2(ys[a0], ys[a1]);
            Zp[p] = pk2(zs[a0], zs[a1]);
            Du[2*p] = __float_as_uint(1e10f); Du[2*p+1] = __float_as_uint(1e10f);
        }
        if (t == 0) g_fps[b*MPTS] = g_oi[b*NPTS];
        float px = xs[0], py = ys[0], pz = zs[0];
        int par = 0;

        for (int m = 1; m < MPTS; m++){
            /* ---- region A: distance updates + local max ---- */
            ull nx = pk2(-px, -px), ny = pk2(-py, -py), nz = pk2(-pz, -pz);
            unsigned v[PMAX/2];
            #pragma unroll
            for (int p = 0; p < PMAX/2; p++){
                ull dx = add2(Xp[p], nx);               /* x - px        */
                ull dy = add2(Yp[p], ny);
                ull dz = add2(Zp[p], nz);
                ull s  = add2(add2(mul2(dx,dx), mul2(dy,dy)), mul2(dz,dz));
                float d0, d1; upk2(s, d0, d1);
                unsigned n0 = min(Du[2*p],   __float_as_uint(d0));
                unsigned n1 = min(Du[2*p+1], __float_as_uint(d1));
                Du[2*p] = n0; Du[2*p+1] = n1;
                v[p] = max(n0, n1);
            }
            /* 11 -> 1 max tree, depth 5 */
            unsigned m0 = max(v[0], v[1]);
            unsigned m1 = max(v[2], v[3]);
            unsigned m2 = max(v[4], v[5]);
            unsigned m3 = max(v[6], v[7]);
            unsigned m4 = max(v[8], v[9]);
            unsigned n0 = max(m0, m1);
            unsigned n1 = max(m2, m3);
            unsigned n2 = max(m4, v[10]);
            unsigned localmax = max(max(n0, n1), n2);

            unsigned wmax = __reduce_max_sync(0xffffffffu, localmax);
            if (lane == 0) redW[w] = wmax;
            __syncthreads();  /* bar1 */

            /* ---- region B: block max, winner scan, reset other slot ---- */
            unsigned rv = (lane < 16) ? redW[lane] : 0u;
            unsigned bmax = __reduce_max_sync(0xffffffffu, rv);
            if (localmax == bmax){
                int c = 0x7fffffff;
                #pragma unroll
                for (int i = 0; i < PMAX; i++)
                    if (Du[i] == bmax) c = min(c, t + i*TFPS);
                atomicMin(&bciA[par], c);
            }
            if (t == 0) bciA[par ^ 1] = 0x7fffffff;
            __syncthreads();  /* bar2 */

            int wc = bciA[par];
            if (t == 0) g_fps[b*MPTS + m] = g_oi[b*NPTS + wc];
            px = xs[wc]; py = ys[wc]; pz = zs[wc];
            par ^= 1;
        }
    } else {
        /* fallback: dists in smem (reuse coord region), coords from global */
        float* dst = xs;
        float* redD = (float*)scan;          /* reuse */
        int*   redC = (int*)(redD + 16);
        int*   bci  = redC + 16;
        for (int c = t; c < Nv; c += TFPS) dst[c] = 1e10f;
        if (t == 0) g_fps[b*MPTS] = g_oi[b*NPTS];
        __syncthreads();
        float px = g_cc[(size_t)b*NPTS*3+0];
        float py = g_cc[(size_t)b*NPTS*3+1];
        float pz = g_cc[(size_t)b*NPTS*3+2];
        for (int m = 1; m < MPTS; m++){
            float bestd = -1.0f; int bestc = 0x7fffffff;
            for (int c = t; c < Nv; c += TFPS){
                const float* P = &g_cc[((size_t)b*NPTS + c)*3];
                float dx = __fadd_rn(P[0], -px);
                float dy = __fadd_rn(P[1], -py);
                float dz = __fadd_rn(P[2], -pz);
                float d  = __fadd_rn(__fadd_rn(__fmul_rn(dx,dx), __fmul_rn(dy,dy)),
                                     __fmul_rn(dz,dz));
                float nd = fminf(dst[c], d);
                dst[c] = nd;
                if (nd > bestd){ bestd = nd; bestc = c; }
            }
            int wc = block_argmax(bestd, bestc, redD, redC, bci, t);
            if (t == 0) g_fps[b*MPTS + m] = g_oi[b*NPTS + wc];
            const float* P = &g_cc[((size_t)b*NPTS + wc)*3];
            px = P[0]; py = P[1]; pz = P[2];
            __syncthreads();
        }
    }
}

/* ---------- gather xyz + features by FPS indices ---------- */
__global__ void gather_kernel(const float* __restrict__ xyz, const float* __restrict__ feat,
                              float* __restrict__ oxyz, float* __restrict__ ofeat){
    int m = blockIdx.x, b = blockIdx.y;
    int j = g_fps[b*MPTS + m];
    int c = threadIdx.x;
    ofeat[((size_t)(b*MPTS + m))*CDIM + c] = feat[((size_t)b*NPTS + j)*CDIM + c];
    if (c < 3)
        oxyz[((size_t)(b*MPTS + m))*3 + c] = xyz[((size_t)b*NPTS + j)*3 + c];
}

/* ---------- stage 2: 2-NN affordance (d2 = sn + sq - 2*dot, as written) ---------- */
__global__ void nn_kernel(const float* __restrict__ dense, const float* __restrict__ sparse,
                          const float* __restrict__ scores, float* __restrict__ aff){
    __shared__ float sx[NS], sy[NS], sz[NS], sq[NS], sc[NS];
    __shared__ unsigned char sv[NS];
    int b = blockIdx.y;
    for (int i = threadIdx.x; i < NS; i += blockDim.x){
        float x = sparse[((size_t)b*NS + i)*3+0];
        float y = sparse[((size_t)b*NS + i)*3+1];
        float z = sparse[((size_t)b*NS + i)*3+2];
        sx[i]=x; sy[i]=y; sz[i]=z;
        sq[i] = __fadd_rn(__fadd_rn(__fmul_rn(x,x), __fmul_rn(y,y)), __fmul_rn(z,z));
        sv[i] = (x != 0.f || y != 0.f || z != 0.f) ? 1 : 0;
        sc[i] = scores[b*NS + i];
    }
    __syncthreads();
    int j = blockIdx.x * blockDim.x + threadIdx.x;
    float x = dense[((size_t)b*ND + j)*3+0];
    float y = dense[((size_t)b*ND + j)*3+1];
    float z = dense[((size_t)b*ND + j)*3+2];
    float sn = __fadd_rn(__fadd_rn(__fmul_rn(x,x), __fmul_rn(y,y)), __fmul_rn(z,z));
    float d1 = 3.3e38f, d2 = 3.3e38f; int i1 = 0, i2 = 0;
    for (int i = 0; i < NS; i++){
        float dot = __fadd_rn(__fadd_rn(__fmul_rn(x,sx[i]), __fmul_rn(y,sy[i])),
                              __fmul_rn(z,sz[i]));
        float dd  = sv[i] ? __fadd_rn(__fadd_rn(sn, sq[i]), __fmul_rn(-2.0f, dot)) : 1e10f;
        if (dd < d1){ d2 = d1; i2 = i1; d1 = dd; i1 = i; }
        else if (dd < d2){ d2 = dd; i2 = i; }
    }
    aff[b*ND + j] = __fmul_rn(__fadd_rn(sc[i1], sc[i2]), 0.5f);
}

/* ---------- stage 3a: best view per approach dir (argmax dot, tie->first) ---------- */
__global__ void vmax_kernel(const float* __restrict__ appr){
    int gtid = blockIdx.x * blockDim.x + threadIdx.x;
    int wid  = gtid >> 5;
    int lane = gtid & 31;
    if (wid >= B_BATCH*NS*3) return;
    const float* a = appr + (size_t)wid * 3;
    float ax = a[0], ay = a[1], az = a[2];
    float bm = -3.3e38f; int bv = 0x7fffffff;
    for (int v = lane; v < NVIEW; v += 32){
        float d = __fadd_rn(__fadd_rn(__fmul_rn(ax, g_views[v*3+0]),
                                      __fmul_rn(ay, g_views[v*3+1])),
                            __fmul_rn(az, g_views[v*3+2]));
        if (d > bm){ bm = d; bv = v; }
    }
    #pragma unroll
    for (int off = 16; off > 0; off >>= 1){
        float od = __shfl_down_sync(0xffffffffu, bm, off);
        int   ov = __shfl_down_sync(0xffffffffu, bv, off);
        if (od > bm || (od == bm && ov < bv)){ bm = od; bv = ov; }
    }
    if (lane == 0) g_vind[wid] = bv;
}

/* ---------- stage 3b: scatter (one thread per (b,n); k ascending -> last wins) ---------- */
__global__ void scatter_kernel(const float* __restrict__ sparse,
                               const float* __restrict__ nvs,
                               const float* __restrict__ ngs,
                               float* __restrict__ vs_out,
                               float* __restrict__ gs_out){
    int idx = blockIdx.x * blockDim.x + threadIdx.x;   /* b*NS + n */
    if (idx >= B_BATCH*NS) return;
    const float* sp = sparse + (size_t)idx * 3;
    float vm = (sp[0] != 0.f || sp[1] != 0.f || sp[2] != 0.f) ? 1.f : 0.f;
    for (int k = 0; k < 3; k++){
        int v = g_vind[idx*3 + k];
        vs_out[(size_t)idx*NVIEW + v] = __fmul_rn(nvs[idx*3 + k], vm);
        const float* src = ngs + ((size_t)(idx*3 + k)) * 84;
        float* dst = gs_out + ((size_t)idx*NVIEW + v) * 84;
        for (int j = 0; j < 84; j++) dst[j] = __fmul_rn(src[j], vm);
    }
}

extern "C" void kernel_launch(void* const* d_in, const int* in_sizes, int n_in,
                              void* d_out, int out_size){
    const float* seed_xyz   = (const float*)d_in[0];
    const float* seed_feat  = (const float*)d_in[1];
    const float* graspness  = (const float*)d_in[2];
    const float* dense      = (const float*)d_in[3];
    const float* sparse     = (const float*)d_in[4];
    const float* nscores    = (const float*)d_in[5];
    const float* appr       = (const float*)d_in[6];
    const float* nviewsc    = (const float*)d_in[7];
    const float* ngraspsc   = (const float*)d_in[8];
    float* out = (float*)d_out;

    static cudaStream_t s2;
    static cudaEvent_t  e1, e2;
    static int init_done = 0;
    size_t fps_smem = 3*(size_t)NVMAX*4 + TFPS*4 + 16*4 + 2*4 + 64;
    if (!init_done){
        cudaStreamCreateWithFlags(&s2, cudaStreamNonBlocking);
        cudaEventCreateWithFlags(&e1, cudaEventDisableTiming);
        cudaEventCreateWithFlags(&e2, cudaEventDisableTiming);
        cudaFuncSetAttribute(fps_kernel, cudaFuncAttributeMaxDynamicSharedMemorySize,
                             (int)fps_smem);
        init_done = 1;
    }

    /* fork side stream (graph-capturable fork/join pattern) */
    cudaEventRecord(e1, 0);
    cudaStreamWaitEvent(s2, e1, 0);

    /* side stream: everything independent of FPS (overlaps the long fps kernel) */
    {
        size_t n4 = (size_t)(B_BATCH*NS*NVIEW + B_BATCH*NS*NVIEW*84) / 4;
        zero_kernel<<<2048, 256, 0, s2>>>((float4*)(out + O_VIEW), n4);
    }
    views_kernel<<<1, 256, 0, s2>>>();
    nn_kernel<<<dim3(ND/256, B_BATCH), 256, 0, s2>>>(dense, sparse, nscores, out + O_AFF);

    /* main stream: fps (launch index 3 of ours -> ncu -s 5 captures it) */
    fps_kernel<<<B_BATCH, TFPS, fps_smem>>>(seed_xyz, graspness);

    vmax_kernel<<<(B_BATCH*NS*3*32 + 255)/256, 256, 0, s2>>>(appr);
    scatter_kernel<<<(B_BATCH*NS + 255)/256, 256, 0, s2>>>(sparse, nviewsc, ngraspsc,
                                                           out + O_VIEW, out + O_GRASP);
    cudaEventRecord(e2, s2);

    gather_kernel<<<dim3(MPTS, B_BATCH), CDIM>>>(seed_xyz, seed_feat,
                                                 out + O_XYZ, out + O_FEAT);
    /* join */
    cudaStreamWaitEvent(0, e2, 0);
    (void)in_sizes; (void)n_in; (void)out_size;
}